// round 10
// baseline (speedup 1.0000x reference)
#include <cuda_runtime.h>
#include <cuda_bf16.h>
#include <math.h>
#include <stdint.h>

#define NB 2
#define LL 1024
#define SS 1024
#define HH 8
#define EE 64
#define KK 6

#define KEXT 384           // 6 split-term K blocks of 64
#define MT 128             // l rows per CTA tile
#define NT 64              // s per chunk
#define NCH (SS/NT)        // 16 chunks
#define ATB (MT*KEXT*2)    // 98304 B (packed)
#define BTB (NT*KEXT*2)    // 49152 B (packed)
#define AST 392            // smem row stride in bf16 (384 + 8 pad)
#define ASTB (AST*2)       // 784 B
#define ASTW (ASTB/4)      // 196 words
#define AUN (MT*(KEXT/8))  // 6144 16B units per A tile
#define BUN (NT*(KEXT/8))  // 3072 16B units per B chunk

// -------- device scratch ---------------------------------------------------
__device__ float g_hsq[(size_t)KK*NB*HH*LL];
__device__ float g_pi[(size_t)NB*HH*LL*KK];
__device__ float g_ksq[(size_t)NB*HH*SS];
__device__ __align__(16) unsigned char g_A[(size_t)KK*NB*HH*8*ATB];
__device__ __align__(16) unsigned char g_B[(size_t)NB*HH*NCH*BTB];
__device__ __align__(16) float g_scr[(size_t)KK*NB*HH*8*NCH*MT*NT]; // p values
__device__ float  g_mc[(size_t)KK*NB*HH*8*NCH*MT*2];  // per (chunk,row,half) max
__device__ float2 g_mz[(size_t)KK*NB*HH*8*MT];

// -------- helpers ----------------------------------------------------------
__device__ __forceinline__ unsigned short bfb(float x) {
  return __bfloat16_as_ushort(__float2bfloat16_rn(x));
}
__device__ __forceinline__ float bff(unsigned short u) {
  return __bfloat162float(__ushort_as_bfloat16(u));
}
__device__ __forceinline__ uint4 pack8(const unsigned short* u) {
  uint4 p;
  p.x = (uint32_t)u[0] | ((uint32_t)u[1] << 16);
  p.y = (uint32_t)u[2] | ((uint32_t)u[3] << 16);
  p.z = (uint32_t)u[4] | ((uint32_t)u[5] << 16);
  p.w = (uint32_t)u[6] | ((uint32_t)u[7] << 16);
  return p;
}
__device__ __forceinline__ void cp_async16(uint32_t dst, const void* src) {
  asm volatile("cp.async.cg.shared.global [%0], [%1], 16;\n" :: "r"(dst), "l"(src));
}
__device__ __forceinline__ void cp_commit() { asm volatile("cp.async.commit_group;\n"); }
template<int N> __device__ __forceinline__ void cp_wait() {
  asm volatile("cp.async.wait_group %0;\n" :: "n"(N));
}
// bf16 m16n8k16 warp MMA (baseline PTX, legal on compute_103 virtual arch)
__device__ __forceinline__ void mma16816(float* d, const uint32_t* a, const uint32_t* b) {
  asm volatile(
    "mma.sync.aligned.m16n8k16.row.col.f32.bf16.bf16.f32 "
    "{%0,%1,%2,%3}, {%4,%5,%6,%7}, {%8,%9}, {%0,%1,%2,%3};"
    : "+f"(d[0]), "+f"(d[1]), "+f"(d[2]), "+f"(d[3])
    : "r"(a[0]), "r"(a[1]), "r"(a[2]), "r"(a[3]), "r"(b[0]), "r"(b[1]));
}

// ---------------------------------------------------------------------------
// Kernel 1: pi, htilde=tanh(qC), hsq, bf16 cascade split -> g_A (packed rows)
// ---------------------------------------------------------------------------
__global__ __launch_bounds__(256) void precompute_kernel(
    const float* __restrict__ q, const float* __restrict__ M,
    const float* __restrict__ C)
{
  int lt = blockIdx.x, h = blockIdx.y;
  int c  = blockIdx.z >> 1;
  int n  = blockIdx.z & 1;
  int l0 = lt * 64;
  int tid = threadIdx.x;
  __shared__ float sq[64][65];
  __shared__ __align__(16) float sc[64][64];
  __shared__ float sz[64][KK];
  __shared__ float spart[64][4];

  for (int idx = tid; idx < 4096; idx += 256) {
    int l = idx >> 6, e = idx & 63;
    sq[l][e] = q[((size_t)((n*LL + l0 + l)*HH + h))*EE + e];
  }
  for (int idx = tid; idx < 4096; idx += 256)
    sc[idx >> 6][idx & 63] = C[(size_t)(c*HH + h)*4096 + idx];
  __syncthreads();

  if (c == 0) {
    for (int t = tid; t < 64*KK; t += 256) {
      int l = t / KK, k = t % KK;
      float a = 0.f;
      for (int e = 0; e < EE; e++) a += sq[l][e] * M[(h*EE + e)*KK + k];
      sz[l][k] = a;
    }
    __syncthreads();
    if (tid < 64) {
      float mx = sz[tid][0];
      #pragma unroll
      for (int k = 1; k < KK; k++) mx = fmaxf(mx, sz[tid][k]);
      float s = 0.f, ev[KK];
      #pragma unroll
      for (int k = 0; k < KK; k++) { ev[k] = __expf(sz[tid][k] - mx); s += ev[k]; }
      float inv = 1.f / s;
      #pragma unroll
      for (int k = 0; k < KK; k++)
        g_pi[((size_t)((n*HH + h)*LL) + l0 + tid)*KK + k] = ev[k]*inv;
    }
  }

  int lq = tid & 63;
  int f0 = (tid >> 6) * 16;     // warp-uniform -> sc reads broadcast
  float a[16];
  #pragma unroll
  for (int j = 0; j < 16; j++) a[j] = 0.f;
  for (int e = 0; e < EE; e++) {
    float qv = sq[lq][e];
    const float4* crow = (const float4*)&sc[e][f0];
    #pragma unroll
    for (int v = 0; v < 4; v++) {
      float4 cv = crow[v];
      a[v*4+0] += qv * cv.x;  a[v*4+1] += qv * cv.y;
      a[v*4+2] += qv * cv.z;  a[v*4+3] += qv * cv.w;
    }
  }

  unsigned short u1[16], u2[16], u3[16];
  float ssq = 0.f;
  #pragma unroll
  for (int j = 0; j < 16; j++) {
    float t = tanhf(a[j]);
    ssq += t * t;
    unsigned short b1 = bfb(t);  float r1 = t - bff(b1);
    unsigned short b2 = bfb(r1); float r2 = r1 - bff(b2);
    u1[j] = b1; u2[j] = b2; u3[j] = bfb(r2);
  }
  spart[lq][tid >> 6] = ssq;

  int lglob = l0 + lq;
  int ltile = lglob >> 7;
  int rA    = lglob & 127;
  size_t tb = ((size_t)(((c*NB + n)*HH + h)*8 + ltile)) * ATB;
  const unsigned short* srcs[6] = {u1, u1, u2, u2, u1, u3};   // A K-blocks
  #pragma unroll
  for (int b = 0; b < 6; b++) {
    size_t o = tb + (size_t)rA*768 + b*128 + f0*2;
    *(uint4*)(g_A + o)      = pack8(srcs[b]);
    *(uint4*)(g_A + o + 16) = pack8(srcs[b] + 8);
  }

  __syncthreads();
  if (tid < 64)
    g_hsq[(size_t)((c*NB + n)*HH + h)*LL + l0 + tid] =
      spart[tid][0] + spart[tid][1] + spart[tid][2] + spart[tid][3];
}

// ---------------------------------------------------------------------------
// Kernel 2: key bf16 split -> g_B (packed rows) + ksq
// ---------------------------------------------------------------------------
__global__ __launch_bounds__(256) void keyprep_kernel(const float* __restrict__ key)
{
  int sc_ = blockIdx.x, h = blockIdx.y, n = blockIdx.z;
  int tid = threadIdx.x;
  int s_l = tid & 63;
  int eg  = tid >> 6;
  int e0  = eg * 16;
  int s_glob = sc_ * 64 + s_l;
  __shared__ float spart[64][4];

  float kv[16];
  const float4* ks = (const float4*)(key + ((size_t)(n*SS + s_glob)*HH + h)*EE + e0);
  #pragma unroll
  for (int v = 0; v < 4; v++) {
    float4 t = ks[v];
    kv[v*4+0] = t.x; kv[v*4+1] = t.y; kv[v*4+2] = t.z; kv[v*4+3] = t.w;
  }

  unsigned short u1[16], u2[16], u3[16];
  float ssq = 0.f;
  #pragma unroll
  for (int j = 0; j < 16; j++) {
    float t = kv[j];
    ssq += t * t;
    unsigned short b1 = bfb(t);  float r1 = t - bff(b1);
    unsigned short b2 = bfb(r1); float r2 = r1 - bff(b2);
    u1[j] = b1; u2[j] = b2; u3[j] = bfb(r2);
  }
  spart[s_l][eg] = ssq;

  size_t tb = ((size_t)((n*HH + h)*NCH + sc_)) * BTB;
  const unsigned short* srcs[6] = {u1, u2, u1, u2, u3, u1};   // B K-blocks
  #pragma unroll
  for (int b = 0; b < 6; b++) {
    size_t o = tb + (size_t)s_l*768 + b*128 + e0*2;
    *(uint4*)(g_B + o)      = pack8(srcs[b]);
    *(uint4*)(g_B + o + 16) = pack8(srcs[b] + 8);
  }

  __syncthreads();
  if (tid < 64)
    g_ksq[(size_t)(n*HH + h)*SS + sc_*64 + tid] =
      spart[tid][0] + spart[tid][1] + spart[tid][2] + spart[tid][3];
}

// ---------------------------------------------------------------------------
// Kernel 3: warp-MMA attention -> p scratch + (m,z). grid (8, H, N*K), 256 thr
// ---------------------------------------------------------------------------
#define OA    0
#define OB    100352          // 128*784
#define OKSQ  200704          // + 2*64*784
#define OKL   204800
#define OHSQ  208896
#define OMZ   209408
#define SM_TC 211968

__device__ __forceinline__ float kfun(int c, float d, float ns) {
  if (c == 0) return d;
  if (c == 1) return -__logf(1.f + ns);
  if (c == 2) return -ns;
  if (c == 3) { float t = d + 1.f; return t * t; }
  if (c == 4) return __expf(-0.5f * ns);
  return __cosf(ns) * __expf(-ns);
}

__global__ __launch_bounds__(256, 1) void attn_mma_kernel(
    const float* __restrict__ mask, const float* __restrict__ keylen)
{
  extern __shared__ __align__(16) char smc[];
  const uint32_t* As32 = (const uint32_t*)(smc + OA);
  float*  s_ksq = (float*)(smc + OKSQ);
  float*  s_kl  = (float*)(smc + OKL);
  float*  s_hsq = (float*)(smc + OHSQ);
  float2* s_mz  = (float2*)(smc + OMZ);
  uint32_t smb = (uint32_t)__cvta_generic_to_shared(smc);
  uint32_t aU  = smb + OA;
  uint32_t bU0 = smb + OB;

  int lt = blockIdx.x, h = blockIdx.y;
  int c  = blockIdx.z >> 1;
  int n  = blockIdx.z & 1;
  int l0 = lt * MT;
  int tid = threadIdx.x;
  int wid = tid >> 5, lane = tid & 31;
  int warp_m = wid & 3, warp_n = wid >> 2;
  int m0  = warp_m * 32;
  int n0w = warp_n * 32;
  int g_  = lane >> 2, tg = lane & 3;

  for (int s = tid; s < SS; s += 256) {
    s_ksq[s] = g_ksq[(size_t)(n*HH + h)*SS + s];
    s_kl[s]  = keylen[(size_t)n*SS + s];
  }
  if (tid < MT)
    s_hsq[tid] = g_hsq[(size_t)((c*NB + n)*HH + h)*LL + l0 + tid];

  // preload A tile (restride 768B -> 784B rows) + B chunk 0
  const unsigned char* gAt = g_A + (size_t)(((c*NB + n)*HH + h)*8 + lt) * ATB;
  const unsigned char* gBb = g_B + (size_t)((n*HH + h)*NCH) * BTB;
  #pragma unroll
  for (int t = 0; t < AUN/256; t++) {
    int idx = tid + t*256;
    int row = idx / 48, u = idx % 48;
    cp_async16(aU + row*ASTB + u*16, gAt + (size_t)idx*16);
  }
  #pragma unroll
  for (int t = 0; t < BUN/256; t++) {
    int idx = tid + t*256;
    int row = idx / 48, u = idx % 48;
    cp_async16(bU0 + row*ASTB + u*16, gBb + (size_t)idx*16);
  }
  cp_commit();
  cp_wait<0>();
  __syncthreads();

  float* scr = g_scr + (size_t)(((c*NB + n)*HH + h)*8 + lt) * ((size_t)NCH*MT*NT);
  float* mcb = g_mc  + (size_t)(((c*NB + n)*HH + h)*8 + lt) * ((size_t)NCH*MT*2);

  float hs_r[4];
  #pragma unroll
  for (int im = 0; im < 2; im++)
    #pragma unroll
    for (int hh = 0; hh < 2; hh++)
      hs_r[im*2 + hh] = s_hsq[m0 + im*16 + hh*8 + g_];

  float m_run[4], z_run[4];
  #pragma unroll
  for (int ri = 0; ri < 4; ri++) { m_run[ri] = -3.4e38f; z_run[ri] = 0.f; }

  #pragma unroll 1
  for (int i = 0; i < NCH; i++) {
    if (i > 0) __syncthreads();           // all warps done reading buf[(i+1)&1]
    if (i + 1 < NCH) {
      uint32_t dst = bU0 + ((i+1) & 1) * (64*ASTB);
      const unsigned char* src = gBb + (size_t)(i+1) * BTB;
      #pragma unroll
      for (int t = 0; t < BUN/256; t++) {
        int idx = tid + t*256;
        int row = idx / 48, u = idx % 48;
        cp_async16(dst + row*ASTB + u*16, src + (size_t)idx*16);
      }
      cp_commit();
      cp_wait<1>();                       // B[i] complete
    } else {
      cp_wait<0>();
    }
    __syncthreads();

    const uint32_t* Bs32 = (const uint32_t*)(smc + OB + (i & 1) * (64*ASTB));

    float acc[2][4][4];
    #pragma unroll
    for (int im = 0; im < 2; im++)
      #pragma unroll
      for (int nf = 0; nf < 4; nf++)
        #pragma unroll
        for (int t = 0; t < 4; t++) acc[im][nf][t] = 0.f;

    #pragma unroll 4
    for (int kk = 0; kk < KEXT/16; kk++) {
      int kw = kk*8 + tg;                 // word offset in row
      uint32_t a[2][4], b[4][2];
      #pragma unroll
      for (int im = 0; im < 2; im++) {
        int r0 = m0 + im*16 + g_;
        a[im][0] = As32[r0*ASTW + kw];
        a[im][1] = As32[(r0+8)*ASTW + kw];
        a[im][2] = As32[r0*ASTW + kw + 4];
        a[im][3] = As32[(r0+8)*ASTW + kw + 4];
      }
      #pragma unroll
      for (int nf = 0; nf < 4; nf++) {
        int nr = n0w + nf*8 + g_;
        b[nf][0] = Bs32[nr*ASTW + kw];
        b[nf][1] = Bs32[nr*ASTW + kw + 4];
      }
      #pragma unroll
      for (int im = 0; im < 2; im++)
        #pragma unroll
        for (int nf = 0; nf < 4; nf++)
          mma16816(acc[im][nf], a[im], b[nf]);
    }

    // ---- epilogue: f -> p = exp(f - m_run), z update, scratch store ----
    #pragma unroll
    for (int im = 0; im < 2; im++) {
      #pragma unroll
      for (int hh = 0; hh < 2; hh++) {
        int ri = im*2 + hh;
        int r  = m0 + im*16 + hh*8 + g_;
        const float* mrow = mask + ((size_t)(n*LL + l0 + r))*SS + i*64;
        float hs = hs_r[ri];
        float fv[8];
        float lm = -3.4e38f;
        #pragma unroll
        for (int nf = 0; nf < 4; nf++) {
          int col = n0w + nf*8 + tg*2;
          float2 mk = *(const float2*)(mrow + col);
          float2 kq = *(const float2*)&s_ksq[i*64 + col];
          float2 kl = *(const float2*)&s_kl[i*64 + col];
          float d0 = acc[im][nf][hh*2+0];
          float d1 = acc[im][nf][hh*2+1];
          float ns0 = hs + kq.x - 2.f*d0;
          float ns1 = hs + kq.y - 2.f*d1;
          float f0v = kfun(c, d0, ns0) + mk.x + kl.x;
          float f1v = kfun(c, d1, ns1) + mk.y + kl.y;
          fv[nf*2+0] = f0v; fv[nf*2+1] = f1v;
          lm = fmaxf(lm, fmaxf(f0v, f1v));
        }
        lm = fmaxf(lm, __shfl_xor_sync(0xffffffffu, lm, 1));
        lm = fmaxf(lm, __shfl_xor_sync(0xffffffffu, lm, 2));
        float mn  = fmaxf(m_run[ri], lm);
        float z   = z_run[ri] * __expf(m_run[ri] - mn);
        float pv[8];
        #pragma unroll
        for (int t = 0; t < 8; t++) { pv[t] = __expf(fv[t] - mn); z += pv[t]; }
        z_run[ri] = z;
        m_run[ri] = mn;
        float* sr = scr + ((size_t)i*MT + r)*NT;
        #pragma unroll
        for (int nf = 0; nf < 4; nf++)
          *(float2*)&sr[n0w + nf*8 + tg*2] = make_float2(pv[nf*2], pv[nf*2+1]);
        if (tg == 0) mcb[((size_t)i*MT + r)*2 + warp_n] = mn;
      }
    }
  }

  // final (m,z) merge: reduce z over tg, then across warp_n halves via smem
  #pragma unroll
  for (int im = 0; im < 2; im++)
    #pragma unroll
    for (int hh = 0; hh < 2; hh++) {
      int ri = im*2 + hh;
      int r  = m0 + im*16 + hh*8 + g_;
      float z = z_run[ri];
      z += __shfl_xor_sync(0xffffffffu, z, 1);
      z += __shfl_xor_sync(0xffffffffu, z, 2);
      if (tg == 0) s_mz[r*2 + warp_n] = make_float2(m_run[ri], z);
    }
  __syncthreads();
  if (tid < MT) {
    float2 a = s_mz[tid*2 + 0], b = s_mz[tid*2 + 1];
    float m = fmaxf(a.x, b.x);
    float z = a.y * __expf(a.x - m) + b.y * __expf(b.x - m);
    g_mz[(size_t)(((c*NB + n)*HH + h)*8 + lt)*MT + tid] = make_float2(m, z);
  }
}

// ---------------------------------------------------------------------------
// Kernel 4: combine -> out = sum_c cf_c * exp(mc - m_c) * p.  grid (8, H, N)
// ---------------------------------------------------------------------------
__global__ __launch_bounds__(256) void combine_kernel(float* __restrict__ out)
{
  __shared__ float s_m[KK][MT];
  __shared__ float s_cf[KK][MT];
  int lt = blockIdx.x, h = blockIdx.y, n = blockIdx.z;
  int l0 = lt * MT;
  int tid = threadIdx.x;

  for (int idx = tid; idx < KK*MT; idx += 256) {
    int c = idx >> 7, r = idx & 127;
    float2 mz = g_mz[(size_t)(((c*NB + n)*HH + h)*8 + lt)*MT + r];
    float pi = g_pi[((size_t)((n*HH + h)*LL) + l0 + r)*KK + c];
    s_m[c][r]  = mz.x;
    s_cf[c][r] = pi / mz.y;
  }
  __syncthreads();

  int r = tid >> 1, half = tid & 1;
  const float* scrp[KK];
  const float* mcp[KK];
  #pragma unroll
  for (int c = 0; c < KK; c++) {
    scrp[c] = g_scr + (size_t)(((c*NB + n)*HH + h)*8 + lt) * ((size_t)NCH*MT*NT);
    mcp[c]  = g_mc  + (size_t)(((c*NB + n)*HH + h)*8 + lt) * ((size_t)NCH*MT*2);
  }

  float mv[KK], cf[KK];
  #pragma unroll
  for (int c = 0; c < KK; c++) { mv[c] = s_m[c][r]; cf[c] = s_cf[c][r]; }

  #pragma unroll 1
  for (int g = 0; g < NCH; g++) {
    float w2[KK];
    #pragma unroll
    for (int c = 0; c < KK; c++)
      w2[c] = cf[c] * __expf(mcp[c][((size_t)g*MT + r)*2 + half] - mv[c]);
    float acc[32];
    #pragma unroll
    for (int t = 0; t < 32; t++) acc[t] = 0.f;
    #pragma unroll
    for (int c = 0; c < KK; c++) {
      const float4* src = (const float4*)(scrp[c] + ((size_t)g*MT + r)*NT + half*32);
      float w = w2[c];
      #pragma unroll
      for (int v = 0; v < 8; v++) {
        float4 f = src[v];
        acc[v*4+0] += w * f.x;  acc[v*4+1] += w * f.y;
        acc[v*4+2] += w * f.z;  acc[v*4+3] += w * f.w;
      }
    }
    float4* od = (float4*)(out + ((size_t)((n*HH + h)*LL) + l0 + r)*SS + g*64 + half*32);
    #pragma unroll
    for (int v = 0; v < 8; v++)
      od[v] = make_float4(acc[v*4], acc[v*4+1], acc[v*4+2], acc[v*4+3]);
  }
}

// ---------------------------------------------------------------------------
extern "C" void kernel_launch(void* const* d_in, const int* in_sizes, int n_in,
                              void* d_out, int out_size)
{
  const float* q    = (const float*)d_in[0];
  const float* key  = (const float*)d_in[1];
  const float* mask = (const float*)d_in[2];
  const float* klen = (const float*)d_in[3];
  const float* M    = (const float*)d_in[4];
  const float* C    = (const float*)d_in[5];
  float* out = (float*)d_out;
  (void)in_sizes; (void)n_in; (void)out_size;

  cudaFuncSetAttribute(attn_mma_kernel,
      cudaFuncAttributeMaxDynamicSharedMemorySize, SM_TC);

  dim3 gpre(LL/64, HH, NB*KK);
  precompute_kernel<<<gpre, 256>>>(q, M, C);
  dim3 gkey(SS/64, HH, NB);
  keyprep_kernel<<<gkey, 256>>>(key);
  dim3 gmma(8, HH, NB*KK);
  attn_mma_kernel<<<gmma, 256, SM_TC>>>(mask, klen);
  dim3 gcmb(8, HH, NB);
  combine_kernel<<<gcmb, 256>>>(out);
}

// round 13
// speedup vs baseline: 1.3141x; 1.3141x over previous
#include <cuda_runtime.h>
#include <cuda_bf16.h>
#include <cuda_fp16.h>
#include <math.h>
#include <stdint.h>

#define NB 2
#define LL 1024
#define SS 1024
#define HH 8
#define EE 64
#define KK 6

#define KEXT 384           // 6 split-term K blocks of 64 (precision-mandated)
#define MT 64              // l rows per CTA tile
#define NT 32              // s per chunk
#define NCH (SS/NT)        // 32 chunks
#define AST  392           // smem row stride (bf16): 384 + 8 pad
#define ASTB (AST*2)       // 784 B
#define ROWU 48            // 16B units per packed 768B row
#define AUN (MT*ROWU)      // 3072 units (A tile)
#define BUN (NT*ROWU)      // 1536 units (B chunk)

// -------- device scratch ---------------------------------------------------
__device__ float g_hsq[(size_t)KK*NB*HH*LL];
__device__ float g_pi[(size_t)NB*HH*LL*KK];
__device__ float g_ksq[(size_t)NB*HH*SS];
__device__ __align__(16) unsigned char g_A[(size_t)KK*NB*HH*LL*768];   // packed bf16 rows
__device__ __align__(16) unsigned char g_B[(size_t)NB*HH*SS*768];
__device__ __align__(16) __half g_scr[(size_t)KK*NB*HH*LL*SS];         // p (fp16), 201MB
__device__ float  g_mc[(size_t)KK*NB*HH*16*NCH*MT*2];                  // chunk maxima
__device__ float2 g_mz[(size_t)KK*NB*HH*16*MT];                        // final (m,z)

// -------- helpers ----------------------------------------------------------
__device__ __forceinline__ unsigned short bfb(float x) {
  return __bfloat16_as_ushort(__float2bfloat16_rn(x));
}
__device__ __forceinline__ float bff(unsigned short u) {
  return __bfloat162float(__ushort_as_bfloat16(u));
}
__device__ __forceinline__ uint4 pack8(const unsigned short* u) {
  uint4 p;
  p.x = (uint32_t)u[0] | ((uint32_t)u[1] << 16);
  p.y = (uint32_t)u[2] | ((uint32_t)u[3] << 16);
  p.z = (uint32_t)u[4] | ((uint32_t)u[5] << 16);
  p.w = (uint32_t)u[6] | ((uint32_t)u[7] << 16);
  return p;
}
__device__ __forceinline__ void cp_async16(uint32_t dst, const void* src) {
  asm volatile("cp.async.cg.shared.global [%0], [%1], 16;\n" :: "r"(dst), "l"(src));
}
__device__ __forceinline__ void cp_commit() { asm volatile("cp.async.commit_group;\n"); }
template<int N> __device__ __forceinline__ void cp_wait() {
  asm volatile("cp.async.wait_group %0;\n" :: "n"(N));
}
__device__ __forceinline__ void ldsm_x4(uint32_t* r, uint32_t addr) {
  asm volatile("ldmatrix.sync.aligned.m8n8.x4.shared.b16 {%0,%1,%2,%3}, [%4];"
               : "=r"(r[0]), "=r"(r[1]), "=r"(r[2]), "=r"(r[3]) : "r"(addr));
}
__device__ __forceinline__ void mma16816(float* d, const uint32_t* a, const uint32_t* b) {
  asm volatile(
    "mma.sync.aligned.m16n8k16.row.col.f32.bf16.bf16.f32 "
    "{%0,%1,%2,%3}, {%4,%5,%6,%7}, {%8,%9}, {%0,%1,%2,%3};"
    : "+f"(d[0]), "+f"(d[1]), "+f"(d[2]), "+f"(d[3])
    : "r"(a[0]), "r"(a[1]), "r"(a[2]), "r"(a[3]), "r"(b[0]), "r"(b[1]));
}

// ---------------------------------------------------------------------------
// Kernel 1: pi, htilde=tanh(qC), hsq, bf16 cascade split -> g_A (packed rows)
// ---------------------------------------------------------------------------
__global__ __launch_bounds__(256) void precompute_kernel(
    const float* __restrict__ q, const float* __restrict__ M,
    const float* __restrict__ C)
{
  int lt = blockIdx.x, h = blockIdx.y;
  int c  = blockIdx.z >> 1;
  int n  = blockIdx.z & 1;
  int l0 = lt * 64;
  int tid = threadIdx.x;
  __shared__ float sq[64][65];
  __shared__ __align__(16) float sc[64][64];
  __shared__ float sz[64][KK];
  __shared__ float spart[64][4];

  for (int idx = tid; idx < 4096; idx += 256) {
    int l = idx >> 6, e = idx & 63;
    sq[l][e] = q[((size_t)((n*LL + l0 + l)*HH + h))*EE + e];
  }
  for (int idx = tid; idx < 4096; idx += 256)
    sc[idx >> 6][idx & 63] = C[(size_t)(c*HH + h)*4096 + idx];
  __syncthreads();

  if (c == 0) {
    for (int t = tid; t < 64*KK; t += 256) {
      int l = t / KK, k = t % KK;
      float a = 0.f;
      for (int e = 0; e < EE; e++) a += sq[l][e] * M[(h*EE + e)*KK + k];
      sz[l][k] = a;
    }
    __syncthreads();
    if (tid < 64) {
      float mx = sz[tid][0];
      #pragma unroll
      for (int k = 1; k < KK; k++) mx = fmaxf(mx, sz[tid][k]);
      float s = 0.f, ev[KK];
      #pragma unroll
      for (int k = 0; k < KK; k++) { ev[k] = __expf(sz[tid][k] - mx); s += ev[k]; }
      float inv = 1.f / s;
      #pragma unroll
      for (int k = 0; k < KK; k++)
        g_pi[((size_t)((n*HH + h)*LL) + l0 + tid)*KK + k] = ev[k]*inv;
    }
  }

  int lq = tid & 63;
  int f0 = (tid >> 6) * 16;
  float a[16];
  #pragma unroll
  for (int j = 0; j < 16; j++) a[j] = 0.f;
  for (int e = 0; e < EE; e++) {
    float qv = sq[lq][e];
    const float4* crow = (const float4*)&sc[e][f0];
    #pragma unroll
    for (int v = 0; v < 4; v++) {
      float4 cv = crow[v];
      a[v*4+0] += qv * cv.x;  a[v*4+1] += qv * cv.y;
      a[v*4+2] += qv * cv.z;  a[v*4+3] += qv * cv.w;
    }
  }

  unsigned short u1[16], u2[16], u3[16];
  float ssq = 0.f;
  #pragma unroll
  for (int j = 0; j < 16; j++) {
    float t = tanhf(a[j]);
    ssq += t * t;
    unsigned short b1 = bfb(t);  float r1 = t - bff(b1);
    unsigned short b2 = bfb(r1); float r2 = r1 - bff(b2);
    u1[j] = b1; u2[j] = b2; u3[j] = bfb(r2);
  }
  spart[lq][tid >> 6] = ssq;

  int lglob = l0 + lq;
  size_t tb = (size_t)((c*NB + n)*HH + h) * ((size_t)LL*768) + (size_t)lglob*768;
  const unsigned short* srcs[6] = {u1, u1, u2, u2, u1, u3};   // A K-blocks
  #pragma unroll
  for (int b = 0; b < 6; b++) {
    size_t o = tb + b*128 + f0*2;
    *(uint4*)(g_A + o)      = pack8(srcs[b]);
    *(uint4*)(g_A + o + 16) = pack8(srcs[b] + 8);
  }

  __syncthreads();
  if (tid < 64)
    g_hsq[(size_t)((c*NB + n)*HH + h)*LL + l0 + tid] =
      spart[tid][0] + spart[tid][1] + spart[tid][2] + spart[tid][3];
}

// ---------------------------------------------------------------------------
// Kernel 2: key bf16 split -> g_B (packed rows) + ksq
// ---------------------------------------------------------------------------
__global__ __launch_bounds__(256) void keyprep_kernel(const float* __restrict__ key)
{
  int sc_ = blockIdx.x, h = blockIdx.y, n = blockIdx.z;
  int tid = threadIdx.x;
  int s_l = tid & 63;
  int eg  = tid >> 6;
  int e0  = eg * 16;
  int s_glob = sc_ * 64 + s_l;
  __shared__ float spart[64][4];

  float kv[16];
  const float4* ks = (const float4*)(key + ((size_t)(n*SS + s_glob)*HH + h)*EE + e0);
  #pragma unroll
  for (int v = 0; v < 4; v++) {
    float4 t = ks[v];
    kv[v*4+0] = t.x; kv[v*4+1] = t.y; kv[v*4+2] = t.z; kv[v*4+3] = t.w;
  }

  unsigned short u1[16], u2[16], u3[16];
  float ssq = 0.f;
  #pragma unroll
  for (int j = 0; j < 16; j++) {
    float t = kv[j];
    ssq += t * t;
    unsigned short b1 = bfb(t);  float r1 = t - bff(b1);
    unsigned short b2 = bfb(r1); float r2 = r1 - bff(b2);
    u1[j] = b1; u2[j] = b2; u3[j] = bfb(r2);
  }
  spart[s_l][eg] = ssq;

  size_t tb = (size_t)(n*HH + h) * ((size_t)SS*768) + (size_t)s_glob*768;
  const unsigned short* srcs[6] = {u1, u2, u1, u2, u3, u1};   // B K-blocks
  #pragma unroll
  for (int b = 0; b < 6; b++) {
    size_t o = tb + b*128 + e0*2;
    *(uint4*)(g_B + o)      = pack8(srcs[b]);
    *(uint4*)(g_B + o + 16) = pack8(srcs[b] + 8);
  }

  __syncthreads();
  if (tid < 64)
    g_ksq[(size_t)(n*HH + h)*SS + sc_*64 + tid] =
      spart[tid][0] + spart[tid][1] + spart[tid][2] + spart[tid][3];
}

// ---------------------------------------------------------------------------
// Kernel 3: warp-MMA attention (ldmatrix + m16n8k16) -> fp16 p scratch + (m,z)
// grid (16 lt, H, N*K) = 1536 CTAs, 256 thr, 2 CTAs/SM.
// Warp tile 16(m) x 16(n); chunk = 32 s; B double-buffered via cp.async.
// ---------------------------------------------------------------------------
#define OA    0
#define OB    50176            // 64*784
#define OKSQ  100352           // + 2*32*784
#define OKL   104448
#define OHSQ  108544
#define OMZ   108800           // 128 float2 = 1024 B -> ends 109824
#define SM_TC 110080           // padded (R11 bug: was 109312 -> s_mz overflow)

__device__ __forceinline__ float kfun(int c, float d, float ns) {
  if (c == 0) return d;
  if (c == 1) return -__logf(1.f + ns);
  if (c == 2) return -ns;
  if (c == 3) { float t = d + 1.f; return t * t; }
  if (c == 4) return __expf(-0.5f * ns);
  return __cosf(ns) * __expf(-ns);
}

__global__ __launch_bounds__(256, 2) void attn_mma_kernel(
    const float* __restrict__ mask, const float* __restrict__ keylen)
{
  extern __shared__ __align__(16) char smc[];
  float*  s_ksq = (float*)(smc + OKSQ);
  float*  s_kl  = (float*)(smc + OKL);
  float*  s_hsq = (float*)(smc + OHSQ);
  float2* s_mz  = (float2*)(smc + OMZ);
  uint32_t smb = (uint32_t)__cvta_generic_to_shared(smc);
  uint32_t aU  = smb + OA;
  uint32_t bU0 = smb + OB;

  int lt = blockIdx.x, h = blockIdx.y;
  int c  = blockIdx.z >> 1;
  int n  = blockIdx.z & 1;
  int l0 = lt * MT;
  int tid = threadIdx.x;
  int wid = tid >> 5, lane = tid & 31;
  int warp_m = wid & 3, warp_n = wid >> 2;    // 4 x 2 warp grid
  int m0 = warp_m * 16;
  int n0 = warp_n * 16;
  int g_ = lane >> 2, tg = lane & 3;

  for (int s = tid; s < SS; s += 256) {
    s_ksq[s] = g_ksq[(size_t)(n*HH + h)*SS + s];
    s_kl[s]  = keylen[(size_t)n*SS + s];
  }
  if (tid < MT)
    s_hsq[tid] = g_hsq[(size_t)((c*NB + n)*HH + h)*LL + l0 + tid];

  const unsigned char* gAt = g_A + (size_t)((c*NB + n)*HH + h)*((size_t)LL*768)
                                 + (size_t)l0*768;
  const unsigned char* gBb = g_B + (size_t)(n*HH + h)*((size_t)SS*768);

  #pragma unroll
  for (int t = 0; t < AUN/256; t++) {
    int idx = tid + t*256;
    int row = idx / ROWU, u = idx % ROWU;
    cp_async16(aU + row*ASTB + u*16, gAt + (size_t)idx*16);
  }
  #pragma unroll
  for (int t = 0; t < BUN/256; t++) {
    int idx = tid + t*256;
    int row = idx / ROWU, u = idx % ROWU;
    cp_async16(bU0 + row*ASTB + u*16, gBb + (size_t)idx*16);
  }
  cp_commit();
  cp_wait<0>();
  __syncthreads();

  int T = ((c*NB + n)*HH + h)*16 + lt;
  __half* scr = g_scr + (size_t)T * ((size_t)NCH*MT*NT);
  float*  mcb = g_mc  + (size_t)T * ((size_t)NCH*MT*2);

  // per-lane ldmatrix base addresses (x4 lane-group layout == mma fragments)
  uint32_t a_base = aU + (uint32_t)(m0 + (lane & 7) + ((lane & 8) ? 8 : 0))*ASTB
                       + ((lane & 16) ? 16u : 0u);
  uint32_t b_off  = (uint32_t)(n0 + (lane & 7) + ((lane & 16) ? 8 : 0))*ASTB
                       + ((lane & 8) ? 16u : 0u);

  float hs0 = s_hsq[m0 + g_], hs1 = s_hsq[m0 + 8 + g_];
  float m_run[2] = {-3.4e38f, -3.4e38f};
  float z_run[2] = {0.f, 0.f};

  #pragma unroll 1
  for (int i = 0; i < NCH; i++) {
    if (i > 0) __syncthreads();
    if (i + 1 < NCH) {
      uint32_t dst = bU0 + ((i+1) & 1) * (NT*ASTB);
      const unsigned char* src = gBb + (size_t)(i+1) * (NT*768);
      #pragma unroll
      for (int t = 0; t < BUN/256; t++) {
        int idx = tid + t*256;
        int row = idx / ROWU, u = idx % ROWU;
        cp_async16(dst + row*ASTB + u*16, src + (size_t)idx*16);
      }
      cp_commit();
      cp_wait<1>();
    } else {
      cp_wait<0>();
    }
    __syncthreads();

    uint32_t b_base = bU0 + (i & 1) * (NT*ASTB) + b_off;

    float acc[2][4];
    #pragma unroll
    for (int nf = 0; nf < 2; nf++)
      #pragma unroll
      for (int t = 0; t < 4; t++) acc[nf][t] = 0.f;

    #pragma unroll 8
    for (int kk = 0; kk < KEXT/16; kk++) {
      uint32_t a[4], b[4];
      ldsm_x4(a, a_base + kk*32);
      ldsm_x4(b, b_base + kk*32);
      mma16816(acc[0], a, b + 0);
      mma16816(acc[1], a, b + 2);
    }

    // ---- epilogue ----
    #pragma unroll
    for (int hh = 0; hh < 2; hh++) {
      int r = m0 + hh*8 + g_;
      const float* mrow = mask + ((size_t)(n*LL + l0 + r))*SS + i*NT;
      float hs = hh ? hs1 : hs0;
      float fv[4];
      float lm = -3.4e38f;
      #pragma unroll
      for (int nf = 0; nf < 2; nf++) {
        int col = n0 + nf*8 + tg*2;
        float2 mk = *(const float2*)(mrow + col);
        float2 kq = *(const float2*)&s_ksq[i*NT + col];
        float2 kl = *(const float2*)&s_kl[i*NT + col];
        float d0 = acc[nf][hh*2+0];
        float d1 = acc[nf][hh*2+1];
        float ns0 = hs + kq.x - 2.f*d0;
        float ns1 = hs + kq.y - 2.f*d1;
        float f0v = kfun(c, d0, ns0) + mk.x + kl.x;
        float f1v = kfun(c, d1, ns1) + mk.y + kl.y;
        fv[nf*2+0] = f0v; fv[nf*2+1] = f1v;
        lm = fmaxf(lm, fmaxf(f0v, f1v));
      }
      lm = fmaxf(lm, __shfl_xor_sync(0xffffffffu, lm, 1));
      lm = fmaxf(lm, __shfl_xor_sync(0xffffffffu, lm, 2));
      float mn = fmaxf(m_run[hh], lm);
      float z  = z_run[hh] * __expf(m_run[hh] - mn);
      float p0 = __expf(fv[0] - mn), p1 = __expf(fv[1] - mn);
      float p2 = __expf(fv[2] - mn), p3 = __expf(fv[3] - mn);
      z += p0 + p1 + p2 + p3;
      z_run[hh] = z;
      m_run[hh] = mn;
      __half* sr = scr + ((size_t)i*MT + r)*NT;
      *(__half2*)&sr[n0 + tg*2]     = __floats2half2_rn(p0, p1);
      *(__half2*)&sr[n0 + 8 + tg*2] = __floats2half2_rn(p2, p3);
      if (tg == 0) mcb[((size_t)i*MT + r)*2 + warp_n] = mn;
    }
  }

  // final (m,z): reduce z over tg, then across the 2 warp_n halves via smem
  #pragma unroll
  for (int hh = 0; hh < 2; hh++) {
    int r = m0 + hh*8 + g_;
    float z = z_run[hh];
    z += __shfl_xor_sync(0xffffffffu, z, 1);
    z += __shfl_xor_sync(0xffffffffu, z, 2);
    if (tg == 0) s_mz[r*2 + warp_n] = make_float2(m_run[hh], z);
  }
  __syncthreads();
  if (tid < MT) {
    float2 a = s_mz[tid*2 + 0], b = s_mz[tid*2 + 1];
    float m = fmaxf(a.x, b.x);
    float z = a.y * __expf(a.x - m) + b.y * __expf(b.x - m);
    g_mz[(size_t)T*MT + tid] = make_float2(m, z);
  }
}

// ---------------------------------------------------------------------------
// Kernel 4: combine -> out = sum_c cf_c * exp(mc - m_c) * p.  grid (16, H, N)
// ---------------------------------------------------------------------------
__global__ __launch_bounds__(256) void combine_kernel(float* __restrict__ out)
{
  __shared__ float s_m[KK][MT];
  __shared__ float s_cf[KK][MT];
  int lt = blockIdx.x, h = blockIdx.y, n = blockIdx.z;
  int l0 = lt * MT;
  int tid = threadIdx.x;

  for (int idx = tid; idx < KK*MT; idx += 256) {
    int c = idx >> 6, r = idx & 63;
    int T = ((c*NB + n)*HH + h)*16 + lt;
    float2 mz = g_mz[(size_t)T*MT + r];
    float pi = g_pi[((size_t)((n*HH + h)*LL) + l0 + r)*KK + c];
    s_m[c][r]  = mz.x;
    s_cf[c][r] = pi / mz.y;
  }
  __syncthreads();

  int r = tid >> 2, q = tid & 3;        // row, col-octet within chunk
  const __half* scrp[KK];
  const float* mcp[KK];
  #pragma unroll
  for (int c = 0; c < KK; c++) {
    int T = ((c*NB + n)*HH + h)*16 + lt;
    scrp[c] = g_scr + (size_t)T * ((size_t)NCH*MT*NT);
    mcp[c]  = g_mc  + (size_t)T * ((size_t)NCH*MT*2);
  }
  float mv[KK], cf[KK];
  #pragma unroll
  for (int c = 0; c < KK; c++) { mv[c] = s_m[c][r]; cf[c] = s_cf[c][r]; }

  #pragma unroll 1
  for (int g = 0; g < NCH; g++) {
    float acc[8];
    #pragma unroll
    for (int t = 0; t < 8; t++) acc[t] = 0.f;
    #pragma unroll
    for (int c = 0; c < KK; c++) {
      float w = cf[c] * __expf(mcp[c][((size_t)g*MT + r)*2 + (q >> 1)] - mv[c]);
      uint4 raw = *(const uint4*)(scrp[c] + ((size_t)g*MT + r)*NT + q*8);
      const __half2* hp = (const __half2*)&raw;
      #pragma unroll
      for (int v = 0; v < 4; v++) {
        float2 p = __half22float2(hp[v]);
        acc[v*2+0] += w * p.x;
        acc[v*2+1] += w * p.y;
      }
    }
    float* od = out + ((size_t)((n*HH + h)*LL) + l0 + r)*SS + g*NT + q*8;
    *(float4*)od       = make_float4(acc[0], acc[1], acc[2], acc[3]);
    *(float4*)(od + 4) = make_float4(acc[4], acc[5], acc[6], acc[7]);
  }
}

// ---------------------------------------------------------------------------
extern "C" void kernel_launch(void* const* d_in, const int* in_sizes, int n_in,
                              void* d_out, int out_size)
{
  const float* q    = (const float*)d_in[0];
  const float* key  = (const float*)d_in[1];
  const float* mask = (const float*)d_in[2];
  const float* klen = (const float*)d_in[3];
  const float* M    = (const float*)d_in[4];
  const float* C    = (const float*)d_in[5];
  float* out = (float*)d_out;
  (void)in_sizes; (void)n_in; (void)out_size;

  cudaFuncSetAttribute(attn_mma_kernel,
      cudaFuncAttributeMaxDynamicSharedMemorySize, SM_TC);

  dim3 gpre(LL/64, HH, NB*KK);
  precompute_kernel<<<gpre, 256>>>(q, M, C);
  dim3 gkey(SS/64, HH, NB);
  keyprep_kernel<<<gkey, 256>>>(key);
  dim3 gmma(16, HH, NB*KK);
  attn_mma_kernel<<<gmma, 256, SM_TC>>>(mask, klen);
  dim3 gcmb(16, HH, NB);
  combine_kernel<<<gcmb, 256>>>(out);
}